// round 5
// baseline (speedup 1.0000x reference)
#include <cuda_runtime.h>

#define NMAX 1048576
#define HMAX (1 << 19)          // 524288 hash slots (actual H ~ 128000)
#define SCAN_THREADS 256
#define SCAN_ELEMS 4
#define SCAN_CHUNK (SCAN_THREADS * SCAN_ELEMS)   // 1024
#define SCAN_BLOCKS (HMAX / SCAN_CHUNK)          // 512
#define PREP_BLOCKS 2048
#define PREP_THREADS 256

// XLA rewrites divide-by-const into multiply-by-reciprocal; 1/0.05f rounds to 20.0f exactly.
#define INV_SIZE 20.0f

// lookback packing: cnt bits[0,24), occ bits[24,50), flag bits[62,64)
#define FLAG_A (1ull << 62)
#define FLAG_P (2ull << 62)
#define VALMASK 0x3FFFFFFFFFFFFFFFull

__device__ __align__(16) int g_count[HMAX];
__device__ __align__(16) int g_cursor[HMAX];
__device__ int g_occ[HMAX];      // g_occ[rank] = slot (compacted occupied slots)
__device__ int g_hash[NMAX];
__device__ int g_sorted[NMAX];
__device__ __align__(16) unsigned long long g_look[SCAN_BLOCKS];
__device__ unsigned int g_bmm[PREP_BLOCKS * 6];
__device__ int g_ctr0;           // self-resetting ticket counter (starts at 0)
__device__ int g_K;              // number of occupied clusters

struct Params { float s0, s1, s2; int d0, d01, d012; int b0; };
__device__ Params g_par;

__device__ __forceinline__ unsigned fenc(float f) {
    unsigned u = __float_as_uint(f);
    return (u & 0x80000000u) ? ~u : (u | 0x80000000u);
}
__device__ __forceinline__ float fdec(unsigned v) {
    return __uint_as_float((v & 0x80000000u) ? (v ^ 0x80000000u) : ~v);
}

__device__ __forceinline__ void zero_range(float4* o4, long long a, long long b,
                                           long long tid, long long nth) {
    float4 z = make_float4(0.f, 0.f, 0.f, 0.f);
    for (long long t = a + tid; t < b; t += nth) __stcs(&o4[t], z);
}

// warp-inclusive scan / reduce on u64 (internal fmt: cnt lo32, occ hi32)
__device__ __forceinline__ unsigned long long wscan(unsigned long long v, int lane) {
    #pragma unroll
    for (int off = 1; off < 32; off <<= 1) {
        unsigned long long u = __shfl_up_sync(0xffffffffu, v, off);
        if (lane >= off) v += u;
    }
    return v;
}
__device__ __forceinline__ unsigned long long wreduce64(unsigned long long v) {
    #pragma unroll
    for (int off = 16; off > 0; off >>= 1)
        v += __shfl_down_sync(0xffffffffu, v, off);
    return v;
}

__device__ __forceinline__ unsigned long long pack_lb(unsigned long long internal) {
    unsigned cnt = (unsigned)internal;
    unsigned occ = (unsigned)(internal >> 32);
    return (unsigned long long)cnt | ((unsigned long long)occ << 24);
}
__device__ __forceinline__ unsigned long long unpack_lb(unsigned long long packed) {
    unsigned long long cnt = packed & 0xFFFFFFull;
    unsigned long long occ = (packed >> 24) & 0x3FFFFFFull;
    return cnt | (occ << 32);
}

// ---------------- fused init + minmax + params ----------------
__global__ void k_prep(const float* __restrict__ pos, const int* __restrict__ batch,
                       float4* o4, float* out, long long out_n, int n,
                       long long za, long long zb) {
    long long tid = (long long)blockIdx.x * blockDim.x + threadIdx.x;
    long long nth = (long long)gridDim.x * blockDim.x;

    for (long long t = tid; t < HMAX / 4; t += nth)
        ((int4*)g_count)[t] = make_int4(0, 0, 0, 0);
    if (tid < SCAN_BLOCKS) g_look[tid] = 0ull;
    zero_range(o4, za, zb, tid, nth);
    for (long long t = (out_n & ~3LL) + tid; t < out_n; t += nth) out[t] = 0.f;

    unsigned lmin[3] = {~0u, ~0u, ~0u}, lmax[3] = {0u, 0u, 0u};
    for (long long i = tid; i < n; i += nth) {
        #pragma unroll
        for (int d = 0; d < 3; d++) {
            unsigned e = fenc(pos[3 * i + d]);
            lmin[d] = min(lmin[d], e);
            lmax[d] = max(lmax[d], e);
        }
    }
    __shared__ unsigned smin[3], smax[3];
    if (threadIdx.x == 0) {
        smin[0] = smin[1] = smin[2] = ~0u;
        smax[0] = smax[1] = smax[2] = 0u;
    }
    __syncthreads();
    #pragma unroll
    for (int d = 0; d < 3; d++) { atomicMin(&smin[d], lmin[d]); atomicMax(&smax[d], lmax[d]); }
    __syncthreads();
    if (threadIdx.x < 3) {
        g_bmm[blockIdx.x * 6 + threadIdx.x] = smin[threadIdx.x];
        g_bmm[blockIdx.x * 6 + 3 + threadIdx.x] = smax[threadIdx.x];
    }
    __threadfence();
    __shared__ int isLast;
    if (threadIdx.x == 0)
        isLast = (atomicAdd(&g_ctr0, 1) == (int)gridDim.x - 1);
    __syncthreads();
    if (!isLast) return;

    unsigned rmin[3] = {~0u, ~0u, ~0u}, rmax[3] = {0u, 0u, 0u};
    for (int b = threadIdx.x; b < PREP_BLOCKS; b += blockDim.x) {
        #pragma unroll
        for (int d = 0; d < 3; d++) {
            rmin[d] = min(rmin[d], g_bmm[b * 6 + d]);
            rmax[d] = max(rmax[d], g_bmm[b * 6 + 3 + d]);
        }
    }
    __syncthreads();
    if (threadIdx.x == 0) {
        smin[0] = smin[1] = smin[2] = ~0u;
        smax[0] = smax[1] = smax[2] = 0u;
    }
    __syncthreads();
    #pragma unroll
    for (int d = 0; d < 3; d++) { atomicMin(&smin[d], rmin[d]); atomicMax(&smax[d], rmax[d]); }
    __syncthreads();
    if (threadIdx.x == 0) {
        int dims[3];
        float s[3];
        #pragma unroll
        for (int d = 0; d < 3; d++) {
            s[d] = fdec(smin[d]);
            float e = fdec(smax[d]);
            dims[d] = (int)(floorf(__fmul_rn(__fsub_rn(e, s[d]), INV_SIZE)) + 1.0f);
        }
        Params p;
        p.s0 = s[0]; p.s1 = s[1]; p.s2 = s[2];
        p.d0 = dims[0];
        p.d01 = dims[0] * dims[1];
        p.d012 = dims[0] * dims[1] * dims[2];
        p.b0 = batch[0];
        g_par = p;
        g_ctr0 = 0;
    }
}

// ---------------- hash + histogram (+ zero share) ----------------
__global__ void k_hash(const float* __restrict__ pos, const int* __restrict__ batch, int n,
                       float4* o4, long long za, long long zb) {
    long long tid = (long long)blockIdx.x * blockDim.x + threadIdx.x;
    long long nth = (long long)gridDim.x * blockDim.x;
    zero_range(o4, za, zb, tid, nth);
    int i = (int)tid;
    if (i >= n) return;
    Params p = g_par;
    float p0 = pos[3 * i + 0], p1 = pos[3 * i + 1], p2 = pos[3 * i + 2];
    int c0 = (int)floorf(__fmul_rn(__fsub_rn(p0, p.s0), INV_SIZE));
    int c1 = (int)floorf(__fmul_rn(__fsub_rn(p1, p.s1), INV_SIZE));
    int c2 = (int)floorf(__fmul_rn(__fsub_rn(p2, p.s2), INV_SIZE));
    int cb = batch[i] - p.b0;
    int h = c0 + c1 * p.d0 + c2 * p.d01 + cb * p.d012;
    g_hash[i] = h;
    atomicAdd(&g_count[h], 1);
}

// ---------------- single-pass scan with decoupled lookback ----------------
__global__ void k_scan(float4* o4, long long za, long long zb) {
    long long tid = (long long)blockIdx.x * blockDim.x + threadIdx.x;
    long long nth = (long long)gridDim.x * blockDim.x;
    zero_range(o4, za, zb, tid, nth);

    int t = threadIdx.x;
    int lane = t & 31, wid = t >> 5;
    int bid = blockIdx.x;
    int eb = bid * SCAN_CHUNK + t * SCAN_ELEMS;
    int4 cv = *(const int4*)&g_count[eb];
    int c[4] = {cv.x, cv.y, cv.z, cv.w};
    unsigned long long loc[4];
    unsigned long long run = 0;
    #pragma unroll
    for (int j = 0; j < SCAN_ELEMS; j++) {
        loc[j] = run;
        run += (unsigned long long)(unsigned)c[j] | ((unsigned long long)(c[j] > 0) << 32);
    }
    unsigned long long inc = wscan(run, lane);
    __shared__ unsigned long long wagg[8];
    __shared__ unsigned long long sExcl;
    if (lane == 31) wagg[wid] = inc;
    __syncthreads();
    unsigned long long woff = 0, btot = 0;
    #pragma unroll
    for (int j = 0; j < 8; j++) {
        unsigned long long v = wagg[j];
        if (j < wid) woff += v;
        btot += v;
    }

    // warp 0: publish aggregate, lookback, publish prefix
    if (wid == 0) {
        if (lane == 0 && bid > 0)
            atomicExch(&g_look[bid], FLAG_A | pack_lb(btot));
        unsigned long long excl = 0;
        if (bid > 0) {
            int look = bid - 1;
            volatile unsigned long long* vl = (volatile unsigned long long*)g_look;
            for (;;) {
                int idx = look - lane;
                unsigned long long v = (idx >= 0) ? vl[idx] : (FLAG_P | 0ull);
                unsigned flag = (unsigned)(v >> 62);
                if (__all_sync(0xffffffffu, flag != 0)) {
                    unsigned pmask = __ballot_sync(0xffffffffu, flag == 2u);
                    int plane = pmask ? (__ffs(pmask) - 1) : 32;
                    unsigned long long contrib = (lane <= plane) ? (v & VALMASK) : 0ull;
                    contrib = wreduce64(contrib);
                    excl += __shfl_sync(0xffffffffu, contrib, 0);
                    if (plane < 32) break;
                    look -= 32;
                }
            }
            excl = unpack_lb(excl);
        }
        if (lane == 0) {
            atomicExch(&g_look[bid], FLAG_P | pack_lb(excl + btot));
            sExcl = excl;
            if (bid == SCAN_BLOCKS - 1)
                g_K = (int)((excl + btot) >> 32);
        }
    }
    __syncthreads();

    unsigned long long pre = sExcl + woff + (inc - run);
    #pragma unroll
    for (int j = 0; j < SCAN_ELEMS; j++) {
        unsigned long long v = pre + loc[j];
        g_cursor[eb + j] = (int)(v & 0xFFFFFFFFull);
        if (c[j] > 0) g_occ[(int)(v >> 32)] = eb + j;
    }
}

// ---------------- scatter (counting sort) (+ zero share) ----------------
__global__ void k_scatter(int n, float4* o4, long long za, long long zb) {
    long long tid = (long long)blockIdx.x * blockDim.x + threadIdx.x;
    long long nth = (long long)gridDim.x * blockDim.x;
    zero_range(o4, za, zb, tid, nth);
    int i = (int)tid;
    if (i >= n) return;
    int h = g_hash[i];
    int p = atomicAdd(&g_cursor[h], 1);
    g_sorted[p] = i;
}

// ---------------- gather: persistent, one warp per occupied cluster ----------------
__global__ void k_gather(const float* __restrict__ x, const float* __restrict__ pos,
                         float* __restrict__ out, int n) {
    int lane = threadIdx.x & 31;
    int warp0 = (blockIdx.x * blockDim.x + threadIdx.x) >> 5;
    int nwarps = (gridDim.x * blockDim.x) >> 5;
    int K = g_K;
    Params pr = g_par;
    const float2* x2 = (const float2*)x;
    const float NEG_INF = __int_as_float(0xff800000);

    for (int w = warp0; w < K; w += nwarps) {
        int slot = g_occ[w];
        int cnt = g_count[slot];
        int end = g_cursor[slot];   // after scatter bump: beg + cnt
        int beg = end - cnt;

        float2 vmax = make_float2(NEG_INF, NEG_INF);
        float px = 0.f, py = 0.f, pz = 0.f;
        for (int b = 0; b < cnt; b += 32) {
            int m = min(cnt - b, 32);
            int idxl = 0;
            if (lane < m) {
                idxl = g_sorted[beg + b + lane];
                const float* pp = pos + 3 * (size_t)idxl;
                px += __ldg(&pp[0]);
                py += __ldg(&pp[1]);
                pz += __ldg(&pp[2]);
            }
            #pragma unroll 8
            for (int j = 0; j < m; j++) {
                int idx = __shfl_sync(0xffffffffu, idxl, j);
                float2 v = __ldcs(&x2[(size_t)idx * 32 + lane]);
                vmax.x = fmaxf(vmax.x, v.x);
                vmax.y = fmaxf(vmax.y, v.y);
            }
        }
        // warp-reduce pos sums
        #pragma unroll
        for (int off = 16; off > 0; off >>= 1) {
            px += __shfl_down_sync(0xffffffffu, px, off);
            py += __shfl_down_sync(0xffffffffu, py, off);
            pz += __shfl_down_sync(0xffffffffu, pz, off);
        }
        __stcs(&((float2*)out)[(size_t)w * 32 + lane], vmax);
        if (lane == 0) {
            float inv_base = (float)cnt;
            size_t pb = (size_t)n * 64 + (size_t)w * 3;
            out[pb + 0] = __fdiv_rn(px, inv_base);
            out[pb + 1] = __fdiv_rn(py, inv_base);
            out[pb + 2] = __fdiv_rn(pz, inv_base);
            out[(size_t)n * 67 + w] = (float)(slot / pr.d012 + pr.b0);
        }
    }
}

// ---------------- launch ----------------
extern "C" void kernel_launch(void* const* d_in, const int* in_sizes, int n_in,
                              void* d_out, int out_size) {
    const float* x = (const float*)d_in[0];
    const float* pos = (const float*)d_in[1];
    const int* batch = (const int*)d_in[2];
    int n = in_sizes[2];
    if (n > NMAX) n = NMAX;
    float* out = (float*)d_out;
    float4* o4 = (float4*)d_out;
    long long Q = (long long)out_size >> 2;

    // zero-work shares: prep 22%, hash 28%, scan 15%, scatter 35%
    long long q1 = (long long)(Q * 22 / 100);
    long long q2 = (long long)(Q * 50 / 100);
    long long q3 = (long long)(Q * 65 / 100);

    int nb = (n + 255) / 256;
    k_prep<<<PREP_BLOCKS, PREP_THREADS>>>(pos, batch, o4, out, (long long)out_size, n, 0, q1);
    k_hash<<<nb, 256>>>(pos, batch, n, o4, q1, q2);
    k_scan<<<SCAN_BLOCKS, SCAN_THREADS>>>(o4, q2, q3);
    k_scatter<<<nb, 256>>>(n, o4, q3, Q);
    k_gather<<<1184, 256>>>(x, pos, out, n);
}

// round 6
// speedup vs baseline: 1.2880x; 1.2880x over previous
#include <cuda_runtime.h>

#define NMAX 1048576
#define HMAX (1 << 19)          // 524288 hash slots (actual H ~ 128000)
#define SCAN_THREADS 256
#define SCAN_ELEMS 4
#define SCAN_CHUNK (SCAN_THREADS * SCAN_ELEMS)   // 1024
#define SCAN_BLOCKS (HMAX / SCAN_CHUNK)          // 512
#define PREP_BLOCKS 1024
#define PREP_THREADS 256

// XLA rewrites divide-by-const into multiply-by-reciprocal; 1/0.05f rounds to 20.0f exactly.
#define INV_SIZE 20.0f

__device__ __align__(16) int g_count[HMAX];
__device__ __align__(16) int g_cursor[HMAX];
__device__ int g_occ[HMAX];      // g_occ[rank] = slot (compacted occupied slots)
__device__ int g_hash[NMAX];
__device__ int g_sorted[NMAX];
__device__ __align__(16) unsigned long long g_bsum[SCAN_BLOCKS];
__device__ unsigned int g_bmm[PREP_BLOCKS * 6];
__device__ int g_ctr0;           // self-resetting ticket counters (start at 0)
__device__ int g_ctr1;
__device__ int g_K;              // number of occupied clusters

struct Params { float s0, s1, s2; int d0, d01, d012; int b0; };
__device__ Params g_par;

__device__ __forceinline__ unsigned fenc(float f) {
    unsigned u = __float_as_uint(f);
    return (u & 0x80000000u) ? ~u : (u | 0x80000000u);
}
__device__ __forceinline__ float fdec(unsigned v) {
    return __uint_as_float((v & 0x80000000u) ? (v ^ 0x80000000u) : ~v);
}

__device__ __forceinline__ unsigned long long wscan(unsigned long long v, int lane) {
    #pragma unroll
    for (int off = 1; off < 32; off <<= 1) {
        unsigned long long u = __shfl_up_sync(0xffffffffu, v, off);
        if (lane >= off) v += u;
    }
    return v;
}
__device__ __forceinline__ unsigned long long wreduce64(unsigned long long v) {
    #pragma unroll
    for (int off = 16; off > 0; off >>= 1)
        v += __shfl_down_sync(0xffffffffu, v, off);
    return v;
}

// ---------------- dedicated output zero (parallel branch) ----------------
__global__ void k_zero(float4* o4, float* out, long long out_n) {
    long long tid = (long long)blockIdx.x * blockDim.x + threadIdx.x;
    long long nth = (long long)gridDim.x * blockDim.x;
    long long quads = out_n >> 2;
    float4 z = make_float4(0.f, 0.f, 0.f, 0.f);
    for (long long t = tid; t < quads; t += nth) __stcs(&o4[t], z);
    for (long long t = (quads << 2) + tid; t < out_n; t += nth) out[t] = 0.f;
}

// ---------------- fused init + minmax + params ----------------
__global__ void k_prep(const float* __restrict__ pos, const int* __restrict__ batch, int n) {
    long long tid = (long long)blockIdx.x * blockDim.x + threadIdx.x;
    long long nth = (long long)gridDim.x * blockDim.x;

    for (long long t = tid; t < HMAX / 4; t += nth)
        ((int4*)g_count)[t] = make_int4(0, 0, 0, 0);

    unsigned lmin[3] = {~0u, ~0u, ~0u}, lmax[3] = {0u, 0u, 0u};
    for (long long i = tid; i < n; i += nth) {
        #pragma unroll
        for (int d = 0; d < 3; d++) {
            unsigned e = fenc(pos[3 * i + d]);
            lmin[d] = min(lmin[d], e);
            lmax[d] = max(lmax[d], e);
        }
    }
    __shared__ unsigned smin[3], smax[3];
    if (threadIdx.x == 0) {
        smin[0] = smin[1] = smin[2] = ~0u;
        smax[0] = smax[1] = smax[2] = 0u;
    }
    __syncthreads();
    #pragma unroll
    for (int d = 0; d < 3; d++) { atomicMin(&smin[d], lmin[d]); atomicMax(&smax[d], lmax[d]); }
    __syncthreads();
    if (threadIdx.x < 3) {
        g_bmm[blockIdx.x * 6 + threadIdx.x] = smin[threadIdx.x];
        g_bmm[blockIdx.x * 6 + 3 + threadIdx.x] = smax[threadIdx.x];
    }
    __threadfence();
    __shared__ int isLast;
    if (threadIdx.x == 0)
        isLast = (atomicAdd(&g_ctr0, 1) == (int)gridDim.x - 1);
    __syncthreads();
    if (!isLast) return;

    unsigned rmin[3] = {~0u, ~0u, ~0u}, rmax[3] = {0u, 0u, 0u};
    for (int b = threadIdx.x; b < PREP_BLOCKS; b += blockDim.x) {
        #pragma unroll
        for (int d = 0; d < 3; d++) {
            rmin[d] = min(rmin[d], g_bmm[b * 6 + d]);
            rmax[d] = max(rmax[d], g_bmm[b * 6 + 3 + d]);
        }
    }
    __syncthreads();
    if (threadIdx.x == 0) {
        smin[0] = smin[1] = smin[2] = ~0u;
        smax[0] = smax[1] = smax[2] = 0u;
    }
    __syncthreads();
    #pragma unroll
    for (int d = 0; d < 3; d++) { atomicMin(&smin[d], rmin[d]); atomicMax(&smax[d], rmax[d]); }
    __syncthreads();
    if (threadIdx.x == 0) {
        int dims[3];
        float s[3];
        #pragma unroll
        for (int d = 0; d < 3; d++) {
            s[d] = fdec(smin[d]);
            float e = fdec(smax[d]);
            dims[d] = (int)(floorf(__fmul_rn(__fsub_rn(e, s[d]), INV_SIZE)) + 1.0f);
        }
        Params p;
        p.s0 = s[0]; p.s1 = s[1]; p.s2 = s[2];
        p.d0 = dims[0];
        p.d01 = dims[0] * dims[1];
        p.d012 = dims[0] * dims[1] * dims[2];
        p.b0 = batch[0];
        g_par = p;
        g_ctr0 = 0;
    }
}

// ---------------- hash + histogram ----------------
__global__ void k_hash(const float* __restrict__ pos, const int* __restrict__ batch, int n) {
    int i = blockIdx.x * blockDim.x + threadIdx.x;
    if (i >= n) return;
    Params p = g_par;
    float p0 = pos[3 * i + 0], p1 = pos[3 * i + 1], p2 = pos[3 * i + 2];
    int c0 = (int)floorf(__fmul_rn(__fsub_rn(p0, p.s0), INV_SIZE));
    int c1 = (int)floorf(__fmul_rn(__fsub_rn(p1, p.s1), INV_SIZE));
    int c2 = (int)floorf(__fmul_rn(__fsub_rn(p2, p.s2), INV_SIZE));
    int cb = batch[i] - p.b0;
    int h = c0 + c1 * p.d0 + c2 * p.d01 + cb * p.d012;
    g_hash[i] = h;
    atomicAdd(&g_count[h], 1);
}

// ---------------- scan pass 1: block sums + fused scan of block sums ----------------
__global__ void k_scan1() {
    int t = threadIdx.x;
    int lane = t & 31, wid = t >> 5;
    int4 cv = ((const int4*)g_count)[blockIdx.x * SCAN_THREADS + t];
    unsigned long long s =
        (unsigned long long)(unsigned)(cv.x + cv.y + cv.z + cv.w) |
        ((unsigned long long)((cv.x > 0) + (cv.y > 0) + (cv.z > 0) + (cv.w > 0)) << 32);
    s = wreduce64(s);
    __shared__ unsigned long long wsum[8];
    if (lane == 0) wsum[wid] = s;
    __syncthreads();
    if (t == 0) {
        unsigned long long tot = 0;
        #pragma unroll
        for (int j = 0; j < 8; j++) tot += wsum[j];
        g_bsum[blockIdx.x] = tot;
    }
    __threadfence();
    __shared__ int isLast;
    if (t == 0) isLast = (atomicAdd(&g_ctr1, 1) == (int)gridDim.x - 1);
    __syncthreads();
    if (!isLast) return;

    // exclusive scan of 512 block sums: thread t owns 2 values
    unsigned long long a = g_bsum[2 * t], b = g_bsum[2 * t + 1];
    unsigned long long run = a + b;
    unsigned long long inc = wscan(run, lane);
    __shared__ unsigned long long wagg[8];
    if (lane == 31) wagg[wid] = inc;
    __syncthreads();
    unsigned long long woff = 0;
    #pragma unroll
    for (int j = 0; j < 8; j++) {
        unsigned long long v = wagg[j];
        if (j < wid) woff += v;
    }
    unsigned long long excl = woff + inc - run;
    g_bsum[2 * t] = excl;
    g_bsum[2 * t + 1] = excl + a;
    if (t == SCAN_THREADS - 1) {
        g_K = (int)((woff + inc) >> 32);
        g_ctr1 = 0;
    }
}

// ---------------- scan pass 3: per-element prefixes, cursor + compaction ----------------
__global__ void k_scan3() {
    int t = threadIdx.x;
    int lane = t & 31, wid = t >> 5;
    int eb = blockIdx.x * SCAN_CHUNK + t * SCAN_ELEMS;
    int4 cv = *(const int4*)&g_count[eb];
    int c[4] = {cv.x, cv.y, cv.z, cv.w};
    unsigned long long loc[4];
    unsigned long long run = 0;
    #pragma unroll
    for (int j = 0; j < SCAN_ELEMS; j++) {
        loc[j] = run;
        run += (unsigned long long)(unsigned)c[j] | ((unsigned long long)(c[j] > 0) << 32);
    }
    unsigned long long inc = wscan(run, lane);
    __shared__ unsigned long long wagg[8];
    if (lane == 31) wagg[wid] = inc;
    __syncthreads();
    unsigned long long woff = 0;
    #pragma unroll
    for (int j = 0; j < 8; j++) {
        unsigned long long v = wagg[j];
        if (j < wid) woff += v;
    }
    unsigned long long pre = g_bsum[blockIdx.x] + woff + (inc - run);
    #pragma unroll
    for (int j = 0; j < SCAN_ELEMS; j++) {
        unsigned long long v = pre + loc[j];
        g_cursor[eb + j] = (int)(v & 0xFFFFFFFFull);
        if (c[j] > 0) g_occ[(int)(v >> 32)] = eb + j;
    }
}

// ---------------- scatter (counting sort) ----------------
__global__ void k_scatter(int n) {
    int i = blockIdx.x * blockDim.x + threadIdx.x;
    if (i >= n) return;
    int h = g_hash[i];
    int p = atomicAdd(&g_cursor[h], 1);
    g_sorted[p] = i;
}

// ---------------- gather: persistent, one warp per occupied cluster ----------------
__global__ void k_gather(const float* __restrict__ x, const float* __restrict__ pos,
                         float* __restrict__ out, int n) {
    int lane = threadIdx.x & 31;
    int warp0 = (blockIdx.x * blockDim.x + threadIdx.x) >> 5;
    int nwarps = (gridDim.x * blockDim.x) >> 5;
    int K = g_K;
    Params pr = g_par;
    const float2* x2 = (const float2*)x;
    const float NEG_INF = __int_as_float(0xff800000);

    for (int w = warp0; w < K; w += nwarps) {
        int slot = g_occ[w];
        int cnt = g_count[slot];
        int end = g_cursor[slot];   // after scatter bump: beg + cnt
        int beg = end - cnt;

        float2 vmax = make_float2(NEG_INF, NEG_INF);
        float px = 0.f, py = 0.f, pz = 0.f;
        for (int b = 0; b < cnt; b += 32) {
            int m = min(cnt - b, 32);
            int idxl = 0;
            if (lane < m) {
                idxl = g_sorted[beg + b + lane];
                const float* pp = pos + 3 * (size_t)idxl;
                px += __ldg(&pp[0]);
                py += __ldg(&pp[1]);
                pz += __ldg(&pp[2]);
            }
            #pragma unroll 8
            for (int j = 0; j < m; j++) {
                int idx = __shfl_sync(0xffffffffu, idxl, j);
                float2 v = __ldcs(&x2[(size_t)idx * 32 + lane]);
                vmax.x = fmaxf(vmax.x, v.x);
                vmax.y = fmaxf(vmax.y, v.y);
            }
        }
        #pragma unroll
        for (int off = 16; off > 0; off >>= 1) {
            px += __shfl_down_sync(0xffffffffu, px, off);
            py += __shfl_down_sync(0xffffffffu, py, off);
            pz += __shfl_down_sync(0xffffffffu, pz, off);
        }
        __stcs(&((float2*)out)[(size_t)w * 32 + lane], vmax);
        if (lane == 0) {
            float base = (float)cnt;
            size_t pb = (size_t)n * 64 + (size_t)w * 3;
            out[pb + 0] = __fdiv_rn(px, base);
            out[pb + 1] = __fdiv_rn(py, base);
            out[pb + 2] = __fdiv_rn(pz, base);
            out[(size_t)n * 67 + w] = (float)(slot / pr.d012 + pr.b0);
        }
    }
}

// ---------------- launch: fork zeroing onto a parallel stream ----------------
static cudaStream_t s_zero_stream;
static cudaEvent_t s_ev_fork, s_ev_zero;
static int s_inited = 0;

extern "C" void kernel_launch(void* const* d_in, const int* in_sizes, int n_in,
                              void* d_out, int out_size) {
    const float* x = (const float*)d_in[0];
    const float* pos = (const float*)d_in[1];
    const int* batch = (const int*)d_in[2];
    int n = in_sizes[2];
    if (n > NMAX) n = NMAX;
    float* out = (float*)d_out;
    float4* o4 = (float4*)d_out;

    if (!s_inited) {   // one-time infra setup (streams/events, not device memory)
        cudaStreamCreateWithFlags(&s_zero_stream, cudaStreamNonBlocking);
        cudaEventCreateWithFlags(&s_ev_fork, cudaEventDisableTiming);
        cudaEventCreateWithFlags(&s_ev_zero, cudaEventDisableTiming);
        s_inited = 1;
    }

    int nb = (n + 255) / 256;

    // fork: zero branch runs concurrently with the hash/scan/scatter chain
    cudaEventRecord(s_ev_fork, 0);
    cudaStreamWaitEvent(s_zero_stream, s_ev_fork, 0);
    k_zero<<<2048, 256, 0, s_zero_stream>>>(o4, out, (long long)out_size);
    cudaEventRecord(s_ev_zero, s_zero_stream);

    k_prep<<<PREP_BLOCKS, PREP_THREADS>>>(pos, batch, n);
    k_hash<<<nb, 256>>>(pos, batch, n);
    k_scan1<<<SCAN_BLOCKS, SCAN_THREADS>>>();
    k_scan3<<<SCAN_BLOCKS, SCAN_THREADS>>>();
    k_scatter<<<nb, 256>>>(n);

    // join: gather needs both the sorted lists and the zeroed output
    cudaStreamWaitEvent(0, s_ev_zero, 0);
    k_gather<<<1184, 256>>>(x, pos, out, n);
}

// round 7
// speedup vs baseline: 1.3193x; 1.0243x over previous
#include <cuda_runtime.h>

#define NMAX 1048576
#define HMAX (1 << 19)          // 524288 hash slots (actual H ~ 128000)
#define SCAN_THREADS 256
#define SCAN_ELEMS 4
#define SCAN_CHUNK (SCAN_THREADS * SCAN_ELEMS)   // 1024
#define SCAN_BLOCKS (HMAX / SCAN_CHUNK)          // 512
#define PREP_BLOCKS 1024
#define PREP_THREADS 256
#define GATHER_BLOCKS 1184
#define GATHER_THREADS 256

// XLA rewrites divide-by-const into multiply-by-reciprocal; 1/0.05f rounds to 20.0f exactly.
#define INV_SIZE 20.0f

__device__ __align__(16) int g_count[HMAX];
__device__ __align__(16) int g_cursor[HMAX];
__device__ int g_occ[HMAX];      // g_occ[rank] = slot (compacted occupied slots)
__device__ int g_hash[NMAX];
__device__ int g_sorted[NMAX];
__device__ __align__(16) unsigned long long g_bsum[SCAN_BLOCKS];
__device__ unsigned int g_bmm[PREP_BLOCKS * 6];
__device__ int g_ctr0;           // self-resetting ticket counters (start at 0)
__device__ int g_ctr1;
__device__ int g_K;              // number of occupied clusters

struct Params { float s0, s1, s2; int d0, d01, d012; int b0; };
__device__ Params g_par;

__device__ __forceinline__ unsigned fenc(float f) {
    unsigned u = __float_as_uint(f);
    return (u & 0x80000000u) ? ~u : (u | 0x80000000u);
}
__device__ __forceinline__ float fdec(unsigned v) {
    return __uint_as_float((v & 0x80000000u) ? (v ^ 0x80000000u) : ~v);
}

__device__ __forceinline__ unsigned long long wscan(unsigned long long v, int lane) {
    #pragma unroll
    for (int off = 1; off < 32; off <<= 1) {
        unsigned long long u = __shfl_up_sync(0xffffffffu, v, off);
        if (lane >= off) v += u;
    }
    return v;
}
__device__ __forceinline__ unsigned long long wreduce64(unsigned long long v) {
    #pragma unroll
    for (int off = 16; off > 0; off >>= 1)
        v += __shfl_down_sync(0xffffffffu, v, off);
    return v;
}

// ---------------- fused init + minmax + params ----------------
__global__ void k_prep(const float* __restrict__ pos, const int* __restrict__ batch, int n) {
    long long tid = (long long)blockIdx.x * blockDim.x + threadIdx.x;
    long long nth = (long long)gridDim.x * blockDim.x;

    for (long long t = tid; t < HMAX / 4; t += nth)
        ((int4*)g_count)[t] = make_int4(0, 0, 0, 0);

    unsigned lmin[3] = {~0u, ~0u, ~0u}, lmax[3] = {0u, 0u, 0u};
    for (long long i = tid; i < n; i += nth) {
        #pragma unroll
        for (int d = 0; d < 3; d++) {
            unsigned e = fenc(pos[3 * i + d]);
            lmin[d] = min(lmin[d], e);
            lmax[d] = max(lmax[d], e);
        }
    }
    __shared__ unsigned smin[3], smax[3];
    if (threadIdx.x == 0) {
        smin[0] = smin[1] = smin[2] = ~0u;
        smax[0] = smax[1] = smax[2] = 0u;
    }
    __syncthreads();
    #pragma unroll
    for (int d = 0; d < 3; d++) { atomicMin(&smin[d], lmin[d]); atomicMax(&smax[d], lmax[d]); }
    __syncthreads();
    if (threadIdx.x < 3) {
        g_bmm[blockIdx.x * 6 + threadIdx.x] = smin[threadIdx.x];
        g_bmm[blockIdx.x * 6 + 3 + threadIdx.x] = smax[threadIdx.x];
    }
    __threadfence();
    __shared__ int isLast;
    if (threadIdx.x == 0)
        isLast = (atomicAdd(&g_ctr0, 1) == (int)gridDim.x - 1);
    __syncthreads();
    if (!isLast) return;

    unsigned rmin[3] = {~0u, ~0u, ~0u}, rmax[3] = {0u, 0u, 0u};
    for (int b = threadIdx.x; b < PREP_BLOCKS; b += blockDim.x) {
        #pragma unroll
        for (int d = 0; d < 3; d++) {
            rmin[d] = min(rmin[d], g_bmm[b * 6 + d]);
            rmax[d] = max(rmax[d], g_bmm[b * 6 + 3 + d]);
        }
    }
    __syncthreads();
    if (threadIdx.x == 0) {
        smin[0] = smin[1] = smin[2] = ~0u;
        smax[0] = smax[1] = smax[2] = 0u;
    }
    __syncthreads();
    #pragma unroll
    for (int d = 0; d < 3; d++) { atomicMin(&smin[d], rmin[d]); atomicMax(&smax[d], rmax[d]); }
    __syncthreads();
    if (threadIdx.x == 0) {
        int dims[3];
        float s[3];
        #pragma unroll
        for (int d = 0; d < 3; d++) {
            s[d] = fdec(smin[d]);
            float e = fdec(smax[d]);
            dims[d] = (int)(floorf(__fmul_rn(__fsub_rn(e, s[d]), INV_SIZE)) + 1.0f);
        }
        Params p;
        p.s0 = s[0]; p.s1 = s[1]; p.s2 = s[2];
        p.d0 = dims[0];
        p.d01 = dims[0] * dims[1];
        p.d012 = dims[0] * dims[1] * dims[2];
        p.b0 = batch[0];
        g_par = p;
        g_ctr0 = 0;
    }
}

// ---------------- hash + histogram ----------------
__global__ void k_hash(const float* __restrict__ pos, const int* __restrict__ batch, int n) {
    int i = blockIdx.x * blockDim.x + threadIdx.x;
    if (i >= n) return;
    Params p = g_par;
    float p0 = pos[3 * i + 0], p1 = pos[3 * i + 1], p2 = pos[3 * i + 2];
    int c0 = (int)floorf(__fmul_rn(__fsub_rn(p0, p.s0), INV_SIZE));
    int c1 = (int)floorf(__fmul_rn(__fsub_rn(p1, p.s1), INV_SIZE));
    int c2 = (int)floorf(__fmul_rn(__fsub_rn(p2, p.s2), INV_SIZE));
    int cb = batch[i] - p.b0;
    int h = c0 + c1 * p.d0 + c2 * p.d01 + cb * p.d012;
    g_hash[i] = h;
    atomicAdd(&g_count[h], 1);
}

// ---------------- scan pass 1: block sums + fused scan of block sums ----------------
__global__ void k_scan1() {
    int t = threadIdx.x;
    int lane = t & 31, wid = t >> 5;
    int4 cv = ((const int4*)g_count)[blockIdx.x * SCAN_THREADS + t];
    unsigned long long s =
        (unsigned long long)(unsigned)(cv.x + cv.y + cv.z + cv.w) |
        ((unsigned long long)((cv.x > 0) + (cv.y > 0) + (cv.z > 0) + (cv.w > 0)) << 32);
    s = wreduce64(s);
    __shared__ unsigned long long wsum[8];
    if (lane == 0) wsum[wid] = s;
    __syncthreads();
    if (t == 0) {
        unsigned long long tot = 0;
        #pragma unroll
        for (int j = 0; j < 8; j++) tot += wsum[j];
        g_bsum[blockIdx.x] = tot;
    }
    __threadfence();
    __shared__ int isLast;
    if (t == 0) isLast = (atomicAdd(&g_ctr1, 1) == (int)gridDim.x - 1);
    __syncthreads();
    if (!isLast) return;

    // exclusive scan of 512 block sums: thread t owns 2 values
    unsigned long long a = g_bsum[2 * t], b = g_bsum[2 * t + 1];
    unsigned long long run = a + b;
    unsigned long long inc = wscan(run, lane);
    __shared__ unsigned long long wagg[8];
    if (lane == 31) wagg[wid] = inc;
    __syncthreads();
    unsigned long long woff = 0;
    #pragma unroll
    for (int j = 0; j < 8; j++) {
        unsigned long long v = wagg[j];
        if (j < wid) woff += v;
    }
    unsigned long long excl = woff + inc - run;
    g_bsum[2 * t] = excl;
    g_bsum[2 * t + 1] = excl + a;
    if (t == SCAN_THREADS - 1) {
        g_K = (int)((woff + inc) >> 32);
        g_ctr1 = 0;
    }
}

// ---------------- scan pass 3: per-element prefixes, cursor + compaction ----------------
__global__ void k_scan3() {
    int t = threadIdx.x;
    int lane = t & 31, wid = t >> 5;
    int eb = blockIdx.x * SCAN_CHUNK + t * SCAN_ELEMS;
    int4 cv = *(const int4*)&g_count[eb];
    int c[4] = {cv.x, cv.y, cv.z, cv.w};
    unsigned long long loc[4];
    unsigned long long run = 0;
    #pragma unroll
    for (int j = 0; j < SCAN_ELEMS; j++) {
        loc[j] = run;
        run += (unsigned long long)(unsigned)c[j] | ((unsigned long long)(c[j] > 0) << 32);
    }
    unsigned long long inc = wscan(run, lane);
    __shared__ unsigned long long wagg[8];
    if (lane == 31) wagg[wid] = inc;
    __syncthreads();
    unsigned long long woff = 0;
    #pragma unroll
    for (int j = 0; j < 8; j++) {
        unsigned long long v = wagg[j];
        if (j < wid) woff += v;
    }
    unsigned long long pre = g_bsum[blockIdx.x] + woff + (inc - run);
    #pragma unroll
    for (int j = 0; j < SCAN_ELEMS; j++) {
        unsigned long long v = pre + loc[j];
        g_cursor[eb + j] = (int)(v & 0xFFFFFFFFull);
        if (c[j] > 0) g_occ[(int)(v >> 32)] = eb + j;
    }
}

// ---------------- scatter (counting sort) ----------------
__global__ void k_scatter(int n) {
    int i = blockIdx.x * blockDim.x + threadIdx.x;
    if (i >= n) return;
    int h = g_hash[i];
    int p = atomicAdd(&g_cursor[h], 1);
    g_sorted[p] = i;
}

// ---------------- gather: pad-zero prologue + one warp per occupied cluster ----------------
__global__ void k_gather(const float* __restrict__ x, const float* __restrict__ pos,
                         float* __restrict__ out, int n) {
    int K = g_K;

    // ---- zero only the padding rows (rows >= K); disjoint from gather's writes ----
    {
        long long tid = (long long)blockIdx.x * blockDim.x + threadIdx.x;
        long long nth = (long long)gridDim.x * blockDim.x;
        float4 z = make_float4(0.f, 0.f, 0.f, 0.f);
        // x_dst pad: floats [K*64, n*64) -> float4 [K*16, n*16), 16B-aligned
        float4* o4 = (float4*)out;
        long long a = (long long)K * 16, b = (long long)n * 16;
        for (long long tq = a + tid; tq < b; tq += nth) __stcs(&o4[tq], z);
        // pos_dst pad: floats [n*64 + K*3, n*64 + n*3)
        long long pa = (long long)n * 64 + (long long)K * 3;
        long long pb = (long long)n * 64 + (long long)n * 3;
        for (long long tq = pa + tid; tq < pb; tq += nth) __stcs(&out[tq], 0.f);
        // batch_dst pad: floats [n*67 + K, n*68)
        long long ba = (long long)n * 67 + K;
        long long bb = (long long)n * 68;
        for (long long tq = ba + tid; tq < bb; tq += nth) __stcs(&out[tq], 0.f);
    }

    int lane = threadIdx.x & 31;
    int warp0 = (blockIdx.x * blockDim.x + threadIdx.x) >> 5;
    int nwarps = (gridDim.x * blockDim.x) >> 5;
    Params pr = g_par;
    const float2* x2 = (const float2*)x;
    const float NEG_INF = __int_as_float(0xff800000);

    for (int w = warp0; w < K; w += nwarps) {
        int slot = g_occ[w];
        int cnt = g_count[slot];
        int end = g_cursor[slot];   // after scatter bump: beg + cnt
        int beg = end - cnt;

        float2 vmax = make_float2(NEG_INF, NEG_INF);
        float px = 0.f, py = 0.f, pz = 0.f;
        for (int b = 0; b < cnt; b += 32) {
            int m = min(cnt - b, 32);
            int idxl = 0;
            if (lane < m) {
                idxl = g_sorted[beg + b + lane];
                const float* pp = pos + 3 * (size_t)idxl;
                px += __ldg(&pp[0]);
                py += __ldg(&pp[1]);
                pz += __ldg(&pp[2]);
            }
            #pragma unroll 8
            for (int j = 0; j < m; j++) {
                int idx = __shfl_sync(0xffffffffu, idxl, j);
                float2 v = __ldcs(&x2[(size_t)idx * 32 + lane]);
                vmax.x = fmaxf(vmax.x, v.x);
                vmax.y = fmaxf(vmax.y, v.y);
            }
        }
        #pragma unroll
        for (int off = 16; off > 0; off >>= 1) {
            px += __shfl_down_sync(0xffffffffu, px, off);
            py += __shfl_down_sync(0xffffffffu, py, off);
            pz += __shfl_down_sync(0xffffffffu, pz, off);
        }
        __stcs(&((float2*)out)[(size_t)w * 32 + lane], vmax);
        if (lane == 0) {
            float base = (float)cnt;
            size_t pb = (size_t)n * 64 + (size_t)w * 3;
            out[pb + 0] = __fdiv_rn(px, base);
            out[pb + 1] = __fdiv_rn(py, base);
            out[pb + 2] = __fdiv_rn(pz, base);
            out[(size_t)n * 67 + w] = (float)(slot / pr.d012 + pr.b0);
        }
    }
}

// ---------------- launch ----------------
extern "C" void kernel_launch(void* const* d_in, const int* in_sizes, int n_in,
                              void* d_out, int out_size) {
    const float* x = (const float*)d_in[0];
    const float* pos = (const float*)d_in[1];
    const int* batch = (const int*)d_in[2];
    int n = in_sizes[2];
    if (n > NMAX) n = NMAX;
    float* out = (float*)d_out;

    int nb = (n + 255) / 256;
    k_prep<<<PREP_BLOCKS, PREP_THREADS>>>(pos, batch, n);
    k_hash<<<nb, 256>>>(pos, batch, n);
    k_scan1<<<SCAN_BLOCKS, SCAN_THREADS>>>();
    k_scan3<<<SCAN_BLOCKS, SCAN_THREADS>>>();
    k_scatter<<<nb, 256>>>(n);
    k_gather<<<GATHER_BLOCKS, GATHER_THREADS>>>(x, pos, out, n);
}